// round 5
// baseline (speedup 1.0000x reference)
#include <cuda_runtime.h>
#include <math.h>

#define MODEL_DIM 256
#define NUM_HEAD  8
#define HEAD_DIM  32
#define SEQ       128
#define BATCH     2
#define ROWS      (BATCH * SEQ * SEQ)   /* 32768 */
#define QKV_DIM   768
#define SCALE     0.17677669529663687f  /* 32^-0.5 */
#define LN_EPS    1e-5f
#define MASK_BIAS -1000000000.0f
#define MASK_N    (BATCH * SEQ * SEQ)   /* 32768 mask elements */

// -------- scratch (static device globals; no runtime allocation) --------
__device__ float g_qkv[(size_t)ROWS * QKV_DIM];      // 96 MB
__device__ float g_attno[(size_t)ROWS * MODEL_DIM];  // 32 MB
__device__ float g_mu[ROWS];
__device__ float g_rstd[ROWS];
__device__ unsigned g_mask_is_u8;                    // 1 => mask stored as 1 byte/elem

// ------------------------------------------------------------------
// K0: detect mask element width.
// If the harness widened bool -> int32/float32, every byte at index i with
// (i % 4 != 0) inside the first MASK_N bytes encodes high bytes of 0/1
// (int32) or low bytes of 0.0f/1.0f (float32) -> all zero... except float32
// 1.0f has bytes [00 00 80 3f]; bytes at i%4==1 are 0 for BOTH widenings.
// So scan only i % 4 == 1. For a random 1-byte mask those are ~50% nonzero.
// Reading i <= MASK_N-3 stays in-bounds for the 1-byte layout too.
// ------------------------------------------------------------------
__global__ void mask_detect_kernel(const unsigned char* __restrict__ m) {
    __shared__ int any;
    if (threadIdx.x == 0) any = 0;
    __syncthreads();
    int found = 0;
    for (int i = threadIdx.x; i < MASK_N / 4; i += blockDim.x) {
        if (m[i * 4 + 1]) found = 1;
    }
    if (found) atomicOr(&any, 1);
    __syncthreads();
    if (threadIdx.x == 0) g_mask_is_u8 = (unsigned)any;
}

// ------------------------------------------------------------------
// K1: layernorm statistics (one warp per row of 256)
// ------------------------------------------------------------------
__global__ __launch_bounds__(256) void ln_stats_kernel(const float* __restrict__ x) {
    int row  = blockIdx.x * 8 + threadIdx.y;
    int lane = threadIdx.x;
    const float* xr = x + (size_t)row * MODEL_DIM;
    float s = 0.f, s2 = 0.f;
#pragma unroll
    for (int i = 0; i < 2; i++) {
        float4 v = reinterpret_cast<const float4*>(xr)[lane + i * 32];
        s  += v.x + v.y + v.z + v.w;
        s2 += v.x * v.x + v.y * v.y + v.z * v.z + v.w * v.w;
    }
#pragma unroll
    for (int o = 16; o; o >>= 1) {
        s  += __shfl_xor_sync(0xffffffffu, s, o);
        s2 += __shfl_xor_sync(0xffffffffu, s2, o);
    }
    if (lane == 0) {
        float mu  = s * (1.0f / MODEL_DIM);
        float var = s2 * (1.0f / MODEL_DIM) - mu * mu;
        g_mu[row]   = mu;
        g_rstd[row] = rsqrtf(var + LN_EPS);
    }
}

// ------------------------------------------------------------------
// K2/K5: SGEMM  C[M,N] = A[M,256] * Bw[N,256]^T, optional fused LN on A
// BM=BN=128, BK=16, 256 threads, 8x8 per thread
// ------------------------------------------------------------------
template <int DO_LN>
__device__ __forceinline__ void gemm_body(const float* __restrict__ A,
                                          const float* __restrict__ Bw,
                                          float* __restrict__ C, int N,
                                          const float* __restrict__ gamma,
                                          const float* __restrict__ beta) {
    const int K = 256;
    __shared__ __align__(16) float As[16][132];
    __shared__ __align__(16) float Bs[16][132];

    int m0  = blockIdx.y * 128;
    int n0  = blockIdx.x * 128;
    int tid = threadIdx.x;
    int tx  = tid & 15;   // n
    int ty  = tid >> 4;   // m

    float acc[8][8];
#pragma unroll
    for (int i = 0; i < 8; i++)
#pragma unroll
        for (int j = 0; j < 8; j++) acc[i][j] = 0.f;

    for (int k0 = 0; k0 < K; k0 += 16) {
#pragma unroll
        for (int u = 0; u < 2; u++) {
            int id  = tid * 2 + u;      // 0..511
            int row = id >> 2;          // 0..127
            int c4  = (id & 3) * 4;     // 0,4,8,12
            float4 v = *(const float4*)(A + (size_t)(m0 + row) * K + k0 + c4);
            if (DO_LN) {
                float mu = g_mu[m0 + row], rs = g_rstd[m0 + row];
                v.x = (v.x - mu) * rs * gamma[k0 + c4 + 0] + beta[k0 + c4 + 0];
                v.y = (v.y - mu) * rs * gamma[k0 + c4 + 1] + beta[k0 + c4 + 1];
                v.z = (v.z - mu) * rs * gamma[k0 + c4 + 2] + beta[k0 + c4 + 2];
                v.w = (v.w - mu) * rs * gamma[k0 + c4 + 3] + beta[k0 + c4 + 3];
            }
            As[c4 + 0][row] = v.x; As[c4 + 1][row] = v.y;
            As[c4 + 2][row] = v.z; As[c4 + 3][row] = v.w;
            float4 w = *(const float4*)(Bw + (size_t)(n0 + row) * K + k0 + c4);
            Bs[c4 + 0][row] = w.x; Bs[c4 + 1][row] = w.y;
            Bs[c4 + 2][row] = w.z; Bs[c4 + 3][row] = w.w;
        }
        __syncthreads();
#pragma unroll
        for (int kk = 0; kk < 16; kk++) {
            float a[8], b[8];
            *(float4*)(&a[0]) = *(const float4*)(&As[kk][ty * 8]);
            *(float4*)(&a[4]) = *(const float4*)(&As[kk][ty * 8 + 4]);
            *(float4*)(&b[0]) = *(const float4*)(&Bs[kk][tx * 8]);
            *(float4*)(&b[4]) = *(const float4*)(&Bs[kk][tx * 8 + 4]);
#pragma unroll
            for (int i = 0; i < 8; i++)
#pragma unroll
                for (int j = 0; j < 8; j++) acc[i][j] += a[i] * b[j];
        }
        __syncthreads();
    }

#pragma unroll
    for (int i = 0; i < 8; i++) {
        float* crow = C + (size_t)(m0 + ty * 8 + i) * N + n0 + tx * 8;
        float4 v0 = make_float4(acc[i][0], acc[i][1], acc[i][2], acc[i][3]);
        float4 v1 = make_float4(acc[i][4], acc[i][5], acc[i][6], acc[i][7]);
        *(float4*)(crow)     = v0;
        *(float4*)(crow + 4) = v1;
    }
}

__global__ __launch_bounds__(256) void qkv_gemm_kernel(const float* __restrict__ A,
                                                       const float* __restrict__ Bw,
                                                       const float* __restrict__ gamma,
                                                       const float* __restrict__ beta) {
    gemm_body<1>(A, Bw, g_qkv, QKV_DIM, gamma, beta);
}

__global__ __launch_bounds__(256) void out_gemm_kernel(const float* __restrict__ Bw,
                                                       float* __restrict__ C) {
    gemm_body<0>(g_attno, Bw, C, MODEL_DIM, nullptr, nullptr);
}

// ------------------------------------------------------------------
// K3: rotary on q[...,0:32] and k[...,0:32] (channels 0..31 and 256..287)
// one warp per row
// ------------------------------------------------------------------
__global__ __launch_bounds__(256) void rotary_kernel() {
    int row = blockIdx.x * 8 + threadIdx.y;
    int d   = threadIdx.x;            // 0..31
    int y   = row & 127;
    int x   = (row >> 7) & 127;
    int j   = (d & 15) >> 1;          // 0..7
    int pos = (d < 16) ? x : y;
    // inv_freq[j] = 10000^(-j/8) ; t = linspace(-1,1,128)
    float invf = exp2f(-(float)j * 1.6609640474436813f);
    float t    = (float)pos * (2.0f / 127.0f) - 1.0f;
    float f    = t * invf;
    float c = cosf(f), s = sinf(f);

    float* qp = g_qkv + (size_t)row * QKV_DIM;
    float qv = qp[d];
    float kv = qp[256 + d];
    float qpart = __shfl_xor_sync(0xffffffffu, qv, 1);
    float kpart = __shfl_xor_sync(0xffffffffu, kv, 1);
    float qrot = (d & 1) ? qpart : -qpart;
    float krot = (d & 1) ? kpart : -kpart;
    qp[d]       = qv * c + qrot * s;
    qp[256 + d] = kv * c + krot * s;
}

// ------------------------------------------------------------------
// K4: attention per (b,x,h). 128 threads = one per query row.
// smem: Ks[128*32] Vs[128*32] Ss[128*129] Mb[128]  = 99328 B
// ------------------------------------------------------------------
__global__ __launch_bounds__(128) void attn_kernel(const void* __restrict__ mask_raw) {
    extern __shared__ float sm[];
    float* Ks = sm;
    float* Vs = Ks + 128 * 32;
    float* Ss = Vs + 128 * 32;
    float* Mb = Ss + 128 * 129;

    int h   = blockIdx.x & 7;
    int bx  = blockIdx.x >> 3;        // 0..255 == (b,x)
    int tid = threadIdx.x;
    size_t base = (size_t)bx * 128;
    int off = h * HEAD_DIM;

    for (int i = tid; i < 128 * 8; i += 128) {
        int r  = i >> 3;
        int f4 = (i & 7) * 4;
        const float* src = g_qkv + (base + r) * QKV_DIM;
        *(float4*)(Ks + r * 32 + f4) = *(const float4*)(src + 256 + off + f4);
        *(float4*)(Vs + r * 32 + f4) = *(const float4*)(src + 512 + off + f4);
    }
    // Mask read: nonzero-word test handles both int32 (0/1) and float32
    // (0.0f/1.0f) widenings; u8 path covers a 1-byte layout.
    {
        size_t mi = (size_t)bx * 128 + tid;
        unsigned mv;
        if (g_mask_is_u8) {
            mv = ((const unsigned char*)mask_raw)[mi];
        } else {
            mv = ((const unsigned int*)mask_raw)[mi];
        }
        Mb[tid] = (mv != 0u) ? 1.0f : 0.0f;
    }

    float q[32];
    const float* qsrc = g_qkv + (base + tid) * QKV_DIM + off;
#pragma unroll
    for (int i = 0; i < 8; i++) *(float4*)(q + i * 4) = *(const float4*)(qsrc + i * 4);
    __syncthreads();

    float* srow = Ss + tid * 129;
    float m = -3.0e38f;
    for (int k = 0; k < 128; k++) {
        float dot = 0.f;
#pragma unroll
        for (int d = 0; d < 32; d += 4) {
            float4 kv = *(const float4*)(Ks + k * 32 + d);
            dot += q[d] * kv.x + q[d + 1] * kv.y + q[d + 2] * kv.z + q[d + 3] * kv.w;
        }
        float sc = (Mb[k] != 0.f) ? MASK_BIAS : dot * SCALE;
        srow[k] = sc;
        m = fmaxf(m, sc);
    }
    float sum = 0.f;
    for (int k = 0; k < 128; k++) {
        float p = __expf(srow[k] - m);
        srow[k] = p;
        sum += p;
    }
    float inv = 1.0f / sum;

    float acc[32];
#pragma unroll
    for (int d = 0; d < 32; d++) acc[d] = 0.f;
    for (int k = 0; k < 128; k++) {
        float p = srow[k];
#pragma unroll
        for (int d = 0; d < 32; d += 4) {
            float4 v = *(const float4*)(Vs + k * 32 + d);
            acc[d]     += p * v.x;
            acc[d + 1] += p * v.y;
            acc[d + 2] += p * v.z;
            acc[d + 3] += p * v.w;
        }
    }
    float* dst = g_attno + (base + tid) * MODEL_DIM + off;
#pragma unroll
    for (int i = 0; i < 8; i++) {
        float4 v = make_float4(acc[i * 4] * inv, acc[i * 4 + 1] * inv,
                               acc[i * 4 + 2] * inv, acc[i * 4 + 3] * inv);
        *(float4*)(dst + i * 4) = v;
    }
}

// ------------------------------------------------------------------
extern "C" void kernel_launch(void* const* d_in, const int* in_sizes, int n_in,
                              void* d_out, int out_size) {
    const float* pair_act  = (const float*)d_in[0];
    const void*  pair_mask = (const void*)d_in[1];
    const float* ln_gamma  = (const float*)d_in[2];
    const float* ln_beta   = (const float*)d_in[3];
    const float* Wqkv      = (const float*)d_in[4];
    const float* Wout      = (const float*)d_in[5];
    float*       out       = (float*)d_out;

    (void)in_sizes; (void)n_in; (void)out_size;

    cudaFuncSetAttribute(attn_kernel, cudaFuncAttributeMaxDynamicSharedMemorySize, 99328);

    mask_detect_kernel<<<1, 256>>>((const unsigned char*)pair_mask);
    ln_stats_kernel<<<ROWS / 8, dim3(32, 8)>>>(pair_act);
    qkv_gemm_kernel<<<dim3(QKV_DIM / 128, ROWS / 128), 256>>>(pair_act, Wqkv, ln_gamma, ln_beta);
    rotary_kernel<<<ROWS / 8, dim3(32, 8)>>>();
    attn_kernel<<<BATCH * SEQ * NUM_HEAD, 128, 99328>>>(pair_mask);
    out_gemm_kernel<<<dim3(MODEL_DIM / 128, ROWS / 128), 256>>>(Wout, out);
}

// round 8
// speedup vs baseline: 1.5378x; 1.5378x over previous
#include <cuda_runtime.h>
#include <cuda_bf16.h>
#include <math.h>
#include <stdint.h>

#define MODEL_DIM 256
#define NUM_HEAD  8
#define HEAD_DIM  32
#define SEQ       128
#define BATCH     2
#define ROWS      (BATCH * SEQ * SEQ)   /* 32768 */
#define QKV_DIM   768
#define SCALE     0.17677669529663687f  /* 32^-0.5 */
#define LN_EPS    1e-5f
#define MASK_BIAS -1000000000.0f
#define MASK_N    (BATCH * SEQ * SEQ)

// -------- scratch (static device globals; no runtime allocation) --------
__device__ float g_qkv[(size_t)ROWS * QKV_DIM];            // 96 MB
__device__ float g_attno[(size_t)ROWS * MODEL_DIM];        // 32 MB
__device__ __nv_bfloat16 g_xhi[(size_t)ROWS * MODEL_DIM];
__device__ __nv_bfloat16 g_xlo[(size_t)ROWS * MODEL_DIM];
__device__ __nv_bfloat16 g_ohi[(size_t)ROWS * MODEL_DIM];
__device__ __nv_bfloat16 g_olo[(size_t)ROWS * MODEL_DIM];
__device__ __nv_bfloat16 g_whi[QKV_DIM * MODEL_DIM];
__device__ __nv_bfloat16 g_wlo[QKV_DIM * MODEL_DIM];
__device__ __nv_bfloat16 g_wohi[MODEL_DIM * MODEL_DIM];
__device__ __nv_bfloat16 g_wolo[MODEL_DIM * MODEL_DIM];
__device__ unsigned g_mask_is_u8;

__device__ __forceinline__ uint32_t smem_u32(const void* p) {
    uint32_t a;
    asm("{ .reg .u64 t; cvta.to.shared.u64 t, %1; cvt.u32.u64 %0, t; }" : "=r"(a) : "l"(p));
    return a;
}

#define CP_ASYNC16(saddr, gptr) \
    asm volatile("cp.async.cg.shared.global [%0], [%1], 16;" :: "r"(saddr), "l"(gptr))
#define CP_COMMIT() asm volatile("cp.async.commit_group;" ::: "memory")
#define CP_WAIT0()  asm volatile("cp.async.wait_group 0;" ::: "memory")

#define LDMATRIX_X4(r0, r1, r2, r3, addr) \
    asm volatile("ldmatrix.sync.aligned.m8n8.x4.shared.b16 {%0,%1,%2,%3}, [%4];" \
                 : "=r"(r0), "=r"(r1), "=r"(r2), "=r"(r3) : "r"(addr))

#define MMA_BF16(d, a, b) \
    asm volatile("mma.sync.aligned.m16n8k16.row.col.f32.bf16.bf16.f32 " \
                 "{%0,%1,%2,%3}, {%4,%5,%6,%7}, {%8,%9}, {%0,%1,%2,%3};" \
                 : "+f"((d)[0]), "+f"((d)[1]), "+f"((d)[2]), "+f"((d)[3]) \
                 : "r"((a)[0]), "r"((a)[1]), "r"((a)[2]), "r"((a)[3]), \
                   "r"((b)[0]), "r"((b)[1]))

// ------------------------------------------------------------------
// K0: detect mask element width. Word widenings of 0/1 (int32 or float32)
// have byte i%4==1 always zero; a 1-byte random mask does not.
// ------------------------------------------------------------------
__global__ void mask_detect_kernel(const unsigned char* __restrict__ m) {
    __shared__ int any;
    if (threadIdx.x == 0) any = 0;
    __syncthreads();
    int found = 0;
    for (int i = threadIdx.x; i < MASK_N / 4; i += blockDim.x)
        if (m[i * 4 + 1]) found = 1;
    if (found) atomicOr(&any, 1);
    __syncthreads();
    if (threadIdx.x == 0) g_mask_is_u8 = (unsigned)any;
}

// ------------------------------------------------------------------
// K1: fused LayerNorm + split-bf16 conversion. One warp per row of 256.
// ------------------------------------------------------------------
__global__ __launch_bounds__(256) void ln_conv_kernel(const float* __restrict__ x,
                                                      const float* __restrict__ gamma,
                                                      const float* __restrict__ beta) {
    int row  = blockIdx.x * 8 + threadIdx.y;
    int lane = threadIdx.x;
    const float* xr = x + (size_t)row * MODEL_DIM;
    float4 v[2];
    float s = 0.f, s2 = 0.f;
#pragma unroll
    for (int i = 0; i < 2; i++) {
        v[i] = reinterpret_cast<const float4*>(xr)[lane + i * 32];
        s  += v[i].x + v[i].y + v[i].z + v[i].w;
        s2 += v[i].x * v[i].x + v[i].y * v[i].y + v[i].z * v[i].z + v[i].w * v[i].w;
    }
#pragma unroll
    for (int o = 16; o; o >>= 1) {
        s  += __shfl_xor_sync(0xffffffffu, s, o);
        s2 += __shfl_xor_sync(0xffffffffu, s2, o);
    }
    float mu  = s * (1.0f / MODEL_DIM);
    float var = s2 * (1.0f / MODEL_DIM) - mu * mu;
    float rs  = rsqrtf(var + LN_EPS);
#pragma unroll
    for (int i = 0; i < 2; i++) {
        int c0 = (lane + i * 32) * 4;
        float y[4] = {v[i].x, v[i].y, v[i].z, v[i].w};
#pragma unroll
        for (int j = 0; j < 4; j++)
            y[j] = (y[j] - mu) * rs * gamma[c0 + j] + beta[c0 + j];
        __nv_bfloat16 hi[4], lo[4];
#pragma unroll
        for (int j = 0; j < 4; j++) {
            hi[j] = __float2bfloat16(y[j]);
            lo[j] = __float2bfloat16(y[j] - __bfloat162float(hi[j]));
        }
        size_t o0 = (size_t)row * MODEL_DIM + c0;
        *(__nv_bfloat162*)(g_xhi + o0)     = __nv_bfloat162(hi[0], hi[1]);
        *(__nv_bfloat162*)(g_xhi + o0 + 2) = __nv_bfloat162(hi[2], hi[3]);
        *(__nv_bfloat162*)(g_xlo + o0)     = __nv_bfloat162(lo[0], lo[1]);
        *(__nv_bfloat162*)(g_xlo + o0 + 2) = __nv_bfloat162(lo[2], lo[3]);
    }
}

// ------------------------------------------------------------------
// generic fp32 -> split bf16 conversion (weights, attn output)
// ------------------------------------------------------------------
__global__ __launch_bounds__(256) void conv_kernel(const float* __restrict__ src,
                                                   __nv_bfloat16* __restrict__ hi,
                                                   __nv_bfloat16* __restrict__ lo, int n4) {
    int i = blockIdx.x * blockDim.x + threadIdx.x;
    if (i >= n4) return;
    float4 v = ((const float4*)src)[i];
    float y[4] = {v.x, v.y, v.z, v.w};
    __nv_bfloat16 h[4], l[4];
#pragma unroll
    for (int j = 0; j < 4; j++) {
        h[j] = __float2bfloat16(y[j]);
        l[j] = __float2bfloat16(y[j] - __bfloat162float(h[j]));
    }
    size_t o0 = (size_t)i * 4;
    *(__nv_bfloat162*)(hi + o0)     = __nv_bfloat162(h[0], h[1]);
    *(__nv_bfloat162*)(hi + o0 + 2) = __nv_bfloat162(h[2], h[3]);
    *(__nv_bfloat162*)(lo + o0)     = __nv_bfloat162(l[0], l[1]);
    *(__nv_bfloat162*)(lo + o0 + 2) = __nv_bfloat162(l[2], l[3]);
}

// ------------------------------------------------------------------
// K2/K5: HMMA split-bf16 GEMM.  C[M,N] = A[M,256] * B[N,256]^T
// D = AhiBhi + AhiBlo + AloBhi (fp32 acc).
// Tile 128x128, 256 thr = 8 warps (4m x 2n), warp tile 32x64.
// K chunks of 64; smem per buffer 128 rows x 72 bf16 (144B pitch).
// ------------------------------------------------------------------
#define PITCH     72            /* bf16 elements per smem row */
#define BUF_B     (128 * PITCH * 2)  /* 18432 bytes */
#define GSM_TOTAL (4 * BUF_B)        /* 73728 bytes */

__global__ __launch_bounds__(256) void mma_gemm_kernel(
    const __nv_bfloat16* __restrict__ Ahi, const __nv_bfloat16* __restrict__ Alo,
    const __nv_bfloat16* __restrict__ Bhi, const __nv_bfloat16* __restrict__ Blo,
    float* __restrict__ C, int N) {
    extern __shared__ char smem[];
    uint32_t sbase = smem_u32(smem);
    int tid  = threadIdx.x;
    int lane = tid & 31;
    int wid  = tid >> 5;
    int wm   = wid >> 1;        // 0..3
    int wn   = wid & 1;         // 0..1
    int m0   = blockIdx.y * 128;
    int n0   = blockIdx.x * 128;

    const uint32_t sA_hi = sbase;
    const uint32_t sA_lo = sbase + BUF_B;
    const uint32_t sB_hi = sbase + 2 * BUF_B;
    const uint32_t sB_lo = sbase + 3 * BUF_B;

    float acc[2][8][4];
#pragma unroll
    for (int mt = 0; mt < 2; mt++)
#pragma unroll
        for (int nt = 0; nt < 8; nt++)
#pragma unroll
            for (int j = 0; j < 4; j++) acc[mt][nt][j] = 0.f;

    const uint4* gsrc[4] = {
        (const uint4*)(Ahi + (size_t)m0 * MODEL_DIM),
        (const uint4*)(Alo + (size_t)m0 * MODEL_DIM),
        (const uint4*)(Bhi + (size_t)n0 * MODEL_DIM),
        (const uint4*)(Blo + (size_t)n0 * MODEL_DIM)};

    // ldmatrix lane-invariant address pieces
    int a_row_l = lane & 15;            // + mt*16 + wm*32
    int a_col_l = (lane >> 4) << 3;     // 0 or 8, + k
    int b_row_l = (lane & 7) + ((lane >> 4) & 1) * 8;  // + p*16 + wn*64
    int b_col_l = ((lane >> 3) & 1) << 3;              // + k

    for (int ch = 0; ch < 4; ch++) {
        // -- async load 4 tiles of 128x64 bf16 (1024 x 16B each) --
#pragma unroll
        for (int b = 0; b < 4; b++) {
            const uint4* s = gsrc[b] + ch * 8;  // row stride = 32 uint4
            uint32_t dbase = sbase + b * BUF_B;
#pragma unroll
            for (int it = 0; it < 4; it++) {    // 256 thr x 4 = 1024 (fixed R7 oob)
                int idx = it * 256 + tid;       // 0..1023
                int row = idx >> 3, c = idx & 7;
                CP_ASYNC16(dbase + row * (PITCH * 2) + c * 16,
                           (const void*)(s + (size_t)row * 32 + c));
            }
        }
        CP_COMMIT();
        CP_WAIT0();
        __syncthreads();

        // -- consume: 4 k-steps of 16 --
#pragma unroll
        for (int ks = 0; ks < 4; ks++) {
            int k = ks * 16;
            uint32_t ahi[2][4], alo[2][4], bhi[8][2], blo[8][2];
#pragma unroll
            for (int mt = 0; mt < 2; mt++) {
                uint32_t off = (uint32_t)((wm * 32 + mt * 16 + a_row_l) * (PITCH * 2) +
                                          (k + a_col_l) * 2);
                LDMATRIX_X4(ahi[mt][0], ahi[mt][1], ahi[mt][2], ahi[mt][3], sA_hi + off);
                LDMATRIX_X4(alo[mt][0], alo[mt][1], alo[mt][2], alo[mt][3], sA_lo + off);
            }
#pragma unroll
            for (int p = 0; p < 4; p++) {
                uint32_t off = (uint32_t)((wn * 64 + p * 16 + b_row_l) * (PITCH * 2) +
                                          (k + b_col_l) * 2);
                LDMATRIX_X4(bhi[2 * p][0], bhi[2 * p][1], bhi[2 * p + 1][0], bhi[2 * p + 1][1],
                            sB_hi + off);
                LDMATRIX_X4(blo[2 * p][0], blo[2 * p][1], blo[2 * p + 1][0], blo[2 * p + 1][1],
                            sB_lo + off);
            }
#pragma unroll
            for (int mt = 0; mt < 2; mt++)
#pragma unroll
                for (int nt = 0; nt < 8; nt++) {
                    MMA_BF16(acc[mt][nt], ahi[mt], bhi[nt]);
                    MMA_BF16(acc[mt][nt], ahi[mt], blo[nt]);
                    MMA_BF16(acc[mt][nt], alo[mt], bhi[nt]);
                }
        }
        __syncthreads();
    }

    // -- epilogue --
    int gid  = lane >> 2;
    int tq   = lane & 3;
#pragma unroll
    for (int mt = 0; mt < 2; mt++) {
        int row = m0 + wm * 32 + mt * 16 + gid;
#pragma unroll
        for (int nt = 0; nt < 8; nt++) {
            int col = n0 + wn * 64 + nt * 8 + tq * 2;
            *(float2*)(C + (size_t)row * N + col)       = make_float2(acc[mt][nt][0], acc[mt][nt][1]);
            *(float2*)(C + (size_t)(row + 8) * N + col) = make_float2(acc[mt][nt][2], acc[mt][nt][3]);
        }
    }
}

// ------------------------------------------------------------------
// K3: rotary on q[...,0:32] and k channels [256,288) of g_qkv
// ------------------------------------------------------------------
__global__ __launch_bounds__(256) void rotary_kernel() {
    int row = blockIdx.x * 8 + threadIdx.y;
    int d   = threadIdx.x;
    int y   = row & 127;
    int x   = (row >> 7) & 127;
    int j   = (d & 15) >> 1;
    int pos = (d < 16) ? x : y;
    float invf = exp2f(-(float)j * 1.6609640474436813f);
    float t    = (float)pos * (2.0f / 127.0f) - 1.0f;
    float f    = t * invf;
    float c = cosf(f), s = sinf(f);

    float* qp = g_qkv + (size_t)row * QKV_DIM;
    float qv = qp[d];
    float kv = qp[256 + d];
    float qpart = __shfl_xor_sync(0xffffffffu, qv, 1);
    float kpart = __shfl_xor_sync(0xffffffffu, kv, 1);
    float qrot = (d & 1) ? qpart : -qpart;
    float krot = (d & 1) ? kpart : -kpart;
    qp[d]       = qv * c + qrot * s;
    qp[256 + d] = kv * c + krot * s;
}

// ------------------------------------------------------------------
// K4: attention per (b,x,h). 128 threads = one per query row.
// ------------------------------------------------------------------
__global__ __launch_bounds__(128) void attn_kernel(const void* __restrict__ mask_raw) {
    extern __shared__ float sm[];
    float* Ks = sm;
    float* Vs = Ks + 128 * 32;
    float* Ss = Vs + 128 * 32;
    float* Mb = Ss + 128 * 129;

    int h   = blockIdx.x & 7;
    int bx  = blockIdx.x >> 3;
    int tid = threadIdx.x;
    size_t base = (size_t)bx * 128;
    int off = h * HEAD_DIM;

    for (int i = tid; i < 128 * 8; i += 128) {
        int r  = i >> 3;
        int f4 = (i & 7) * 4;
        const float* src = g_qkv + (base + r) * QKV_DIM;
        *(float4*)(Ks + r * 32 + f4) = *(const float4*)(src + 256 + off + f4);
        *(float4*)(Vs + r * 32 + f4) = *(const float4*)(src + 512 + off + f4);
    }
    {
        size_t mi = (size_t)bx * 128 + tid;
        unsigned mv = g_mask_is_u8 ? (unsigned)((const unsigned char*)mask_raw)[mi]
                                   : ((const unsigned int*)mask_raw)[mi];
        Mb[tid] = (mv != 0u) ? 1.0f : 0.0f;
    }

    float q[32];
    const float* qsrc = g_qkv + (base + tid) * QKV_DIM + off;
#pragma unroll
    for (int i = 0; i < 8; i++) *(float4*)(q + i * 4) = *(const float4*)(qsrc + i * 4);
    __syncthreads();

    float* srow = Ss + tid * 129;
    float m = -3.0e38f;
    for (int k = 0; k < 128; k++) {
        float dot = 0.f;
#pragma unroll
        for (int d = 0; d < 32; d += 4) {
            float4 kv = *(const float4*)(Ks + k * 32 + d);
            dot += q[d] * kv.x + q[d + 1] * kv.y + q[d + 2] * kv.z + q[d + 3] * kv.w;
        }
        float sc = (Mb[k] != 0.f) ? MASK_BIAS : dot * SCALE;
        srow[k] = sc;
        m = fmaxf(m, sc);
    }
    float sum = 0.f;
    for (int k = 0; k < 128; k++) {
        float p = __expf(srow[k] - m);
        srow[k] = p;
        sum += p;
    }
    float inv = 1.0f / sum;

    float acc[32];
#pragma unroll
    for (int d = 0; d < 32; d++) acc[d] = 0.f;
    for (int k = 0; k < 128; k++) {
        float p = srow[k];
#pragma unroll
        for (int d = 0; d < 32; d += 4) {
            float4 v = *(const float4*)(Vs + k * 32 + d);
            acc[d]     += p * v.x;
            acc[d + 1] += p * v.y;
            acc[d + 2] += p * v.z;
            acc[d + 3] += p * v.w;
        }
    }
    float* dst = g_attno + (base + tid) * MODEL_DIM + off;
#pragma unroll
    for (int i = 0; i < 8; i++) {
        float4 v = make_float4(acc[i * 4] * inv, acc[i * 4 + 1] * inv,
                               acc[i * 4 + 2] * inv, acc[i * 4 + 3] * inv);
        *(float4*)(dst + i * 4) = v;
    }
}

// ------------------------------------------------------------------
extern "C" void kernel_launch(void* const* d_in, const int* in_sizes, int n_in,
                              void* d_out, int out_size) {
    const float* pair_act  = (const float*)d_in[0];
    const void*  pair_mask = (const void*)d_in[1];
    const float* ln_gamma  = (const float*)d_in[2];
    const float* ln_beta   = (const float*)d_in[3];
    const float* Wqkv      = (const float*)d_in[4];
    const float* Wout      = (const float*)d_in[5];
    float*       out       = (float*)d_out;

    (void)in_sizes; (void)n_in; (void)out_size;

    cudaFuncSetAttribute(attn_kernel, cudaFuncAttributeMaxDynamicSharedMemorySize, 99328);
    cudaFuncSetAttribute(mma_gemm_kernel, cudaFuncAttributeMaxDynamicSharedMemorySize, GSM_TOTAL);

    __nv_bfloat16 *xhi, *xlo, *ohi, *olo, *whi, *wlo, *wohi, *wolo;
    float *qkv, *attno;
    cudaGetSymbolAddress((void**)&xhi, g_xhi);
    cudaGetSymbolAddress((void**)&xlo, g_xlo);
    cudaGetSymbolAddress((void**)&ohi, g_ohi);
    cudaGetSymbolAddress((void**)&olo, g_olo);
    cudaGetSymbolAddress((void**)&whi, g_whi);
    cudaGetSymbolAddress((void**)&wlo, g_wlo);
    cudaGetSymbolAddress((void**)&wohi, g_wohi);
    cudaGetSymbolAddress((void**)&wolo, g_wolo);
    cudaGetSymbolAddress((void**)&qkv, g_qkv);
    cudaGetSymbolAddress((void**)&attno, g_attno);

    mask_detect_kernel<<<1, 256>>>((const unsigned char*)pair_mask);
    ln_conv_kernel<<<ROWS / 8, dim3(32, 8)>>>(pair_act, ln_gamma, ln_beta);
    conv_kernel<<<(QKV_DIM * MODEL_DIM / 4 + 255) / 256, 256>>>(Wqkv, whi, wlo, QKV_DIM * MODEL_DIM / 4);
    conv_kernel<<<(MODEL_DIM * MODEL_DIM / 4 + 255) / 256, 256>>>(Wout, wohi, wolo, MODEL_DIM * MODEL_DIM / 4);

    mma_gemm_kernel<<<dim3(QKV_DIM / 128, ROWS / 128), 256, GSM_TOTAL>>>(
        xhi, xlo, whi, wlo, qkv, QKV_DIM);

    rotary_kernel<<<ROWS / 8, dim3(32, 8)>>>();
    attn_kernel<<<BATCH * SEQ * NUM_HEAD, 128, 99328>>>(pair_mask);

    conv_kernel<<<((int)((size_t)ROWS * MODEL_DIM / 4) + 255) / 256, 256>>>(
        attno, ohi, olo, (int)((size_t)ROWS * MODEL_DIM / 4));
    mma_gemm_kernel<<<dim3(MODEL_DIM / 128, ROWS / 128), 256, GSM_TOTAL>>>(
        ohi, olo, wohi, wolo, out, MODEL_DIM);
}

// round 9
// speedup vs baseline: 1.7034x; 1.1077x over previous
#include <cuda_runtime.h>
#include <cuda_bf16.h>
#include <math.h>
#include <stdint.h>

#define MODEL_DIM 256
#define NUM_HEAD  8
#define HEAD_DIM  32
#define SEQ       128
#define BATCH     2
#define ROWS      (BATCH * SEQ * SEQ)   /* 32768 */
#define QKV_DIM   768
#define SCALE     0.17677669529663687f  /* 32^-0.5 */
#define LN_EPS    1e-5f
#define MASK_BIAS -1000000000.0f
#define MASK_N    (BATCH * SEQ * SEQ)

// -------- scratch (static device globals; no runtime allocation) --------
__device__ float g_qkv[(size_t)ROWS * QKV_DIM];            // 96 MB
__device__ float g_attno[(size_t)ROWS * MODEL_DIM];        // 32 MB
__device__ __nv_bfloat16 g_xhi[(size_t)ROWS * MODEL_DIM];
__device__ __nv_bfloat16 g_xlo[(size_t)ROWS * MODEL_DIM];
__device__ __nv_bfloat16 g_ohi[(size_t)ROWS * MODEL_DIM];
__device__ __nv_bfloat16 g_olo[(size_t)ROWS * MODEL_DIM];
__device__ __nv_bfloat16 g_whi[QKV_DIM * MODEL_DIM];
__device__ __nv_bfloat16 g_wlo[QKV_DIM * MODEL_DIM];
__device__ __nv_bfloat16 g_wohi[MODEL_DIM * MODEL_DIM];
__device__ __nv_bfloat16 g_wolo[MODEL_DIM * MODEL_DIM];
__device__ unsigned g_mask_is_u8;

__device__ __forceinline__ uint32_t smem_u32(const void* p) {
    uint32_t a;
    asm("{ .reg .u64 t; cvta.to.shared.u64 t, %1; cvt.u32.u64 %0, t; }" : "=r"(a) : "l"(p));
    return a;
}

#define CP_ASYNC16(saddr, gptr) \
    asm volatile("cp.async.cg.shared.global [%0], [%1], 16;" :: "r"(saddr), "l"(gptr))
#define CP_COMMIT() asm volatile("cp.async.commit_group;" ::: "memory")
#define CP_WAIT(n)  asm volatile("cp.async.wait_group %0;" :: "n"(n) : "memory")

#define LDMATRIX_X4(r0, r1, r2, r3, addr) \
    asm volatile("ldmatrix.sync.aligned.m8n8.x4.shared.b16 {%0,%1,%2,%3}, [%4];" \
                 : "=r"(r0), "=r"(r1), "=r"(r2), "=r"(r3) : "r"(addr))

#define MMA_BF16(d, a, b) \
    asm volatile("mma.sync.aligned.m16n8k16.row.col.f32.bf16.bf16.f32 " \
                 "{%0,%1,%2,%3}, {%4,%5,%6,%7}, {%8,%9}, {%0,%1,%2,%3};" \
                 : "+f"((d)[0]), "+f"((d)[1]), "+f"((d)[2]), "+f"((d)[3]) \
                 : "r"((a)[0]), "r"((a)[1]), "r"((a)[2]), "r"((a)[3]), \
                   "r"((b)[0]), "r"((b)[1]))

// ------------------------------------------------------------------
// K0: detect mask element width. Word widenings of 0/1 (int32 or float32)
// have byte i%4==1 always zero; a 1-byte random mask does not.
// ------------------------------------------------------------------
__global__ void mask_detect_kernel(const unsigned char* __restrict__ m) {
    __shared__ int any;
    if (threadIdx.x == 0) any = 0;
    __syncthreads();
    int found = 0;
    for (int i = threadIdx.x; i < MASK_N / 4; i += blockDim.x)
        if (m[i * 4 + 1]) found = 1;
    if (found) atomicOr(&any, 1);
    __syncthreads();
    if (threadIdx.x == 0) g_mask_is_u8 = (unsigned)any;
}

// ------------------------------------------------------------------
// K1: fused LayerNorm + split-bf16 conversion. One warp per row of 256.
// ------------------------------------------------------------------
__global__ __launch_bounds__(256) void ln_conv_kernel(const float* __restrict__ x,
                                                      const float* __restrict__ gamma,
                                                      const float* __restrict__ beta) {
    int row  = blockIdx.x * 8 + threadIdx.y;
    int lane = threadIdx.x;
    const float* xr = x + (size_t)row * MODEL_DIM;
    float4 v[2];
    float s = 0.f, s2 = 0.f;
#pragma unroll
    for (int i = 0; i < 2; i++) {
        v[i] = reinterpret_cast<const float4*>(xr)[lane + i * 32];
        s  += v[i].x + v[i].y + v[i].z + v[i].w;
        s2 += v[i].x * v[i].x + v[i].y * v[i].y + v[i].z * v[i].z + v[i].w * v[i].w;
    }
#pragma unroll
    for (int o = 16; o; o >>= 1) {
        s  += __shfl_xor_sync(0xffffffffu, s, o);
        s2 += __shfl_xor_sync(0xffffffffu, s2, o);
    }
    float mu  = s * (1.0f / MODEL_DIM);
    float var = s2 * (1.0f / MODEL_DIM) - mu * mu;
    float rs  = rsqrtf(var + LN_EPS);
#pragma unroll
    for (int i = 0; i < 2; i++) {
        int c0 = (lane + i * 32) * 4;
        float y[4] = {v[i].x, v[i].y, v[i].z, v[i].w};
#pragma unroll
        for (int j = 0; j < 4; j++)
            y[j] = (y[j] - mu) * rs * gamma[c0 + j] + beta[c0 + j];
        __nv_bfloat16 hi[4], lo[4];
#pragma unroll
        for (int j = 0; j < 4; j++) {
            hi[j] = __float2bfloat16(y[j]);
            lo[j] = __float2bfloat16(y[j] - __bfloat162float(hi[j]));
        }
        size_t o0 = (size_t)row * MODEL_DIM + c0;
        *(__nv_bfloat162*)(g_xhi + o0)     = __nv_bfloat162(hi[0], hi[1]);
        *(__nv_bfloat162*)(g_xhi + o0 + 2) = __nv_bfloat162(hi[2], hi[3]);
        *(__nv_bfloat162*)(g_xlo + o0)     = __nv_bfloat162(lo[0], lo[1]);
        *(__nv_bfloat162*)(g_xlo + o0 + 2) = __nv_bfloat162(lo[2], lo[3]);
    }
}

// ------------------------------------------------------------------
// generic fp32 -> split bf16 conversion (weights, attn output)
// ------------------------------------------------------------------
__global__ __launch_bounds__(256) void conv_kernel(const float* __restrict__ src,
                                                   __nv_bfloat16* __restrict__ hi,
                                                   __nv_bfloat16* __restrict__ lo, int n4) {
    int i = blockIdx.x * blockDim.x + threadIdx.x;
    if (i >= n4) return;
    float4 v = ((const float4*)src)[i];
    float y[4] = {v.x, v.y, v.z, v.w};
    __nv_bfloat16 h[4], l[4];
#pragma unroll
    for (int j = 0; j < 4; j++) {
        h[j] = __float2bfloat16(y[j]);
        l[j] = __float2bfloat16(y[j] - __bfloat162float(h[j]));
    }
    size_t o0 = (size_t)i * 4;
    *(__nv_bfloat162*)(hi + o0)     = __nv_bfloat162(h[0], h[1]);
    *(__nv_bfloat162*)(hi + o0 + 2) = __nv_bfloat162(h[2], h[3]);
    *(__nv_bfloat162*)(lo + o0)     = __nv_bfloat162(l[0], l[1]);
    *(__nv_bfloat162*)(lo + o0 + 2) = __nv_bfloat162(l[2], l[3]);
}

// ------------------------------------------------------------------
// K2/K5: HMMA split-bf16 GEMM, 2-stage cp.async pipeline.
// C[M,N] = A[M,256] * B[N,256]^T; D = AhiBhi + AhiBlo + AloBhi.
// Tile 128x128, 256 thr = 8 warps (4m x 2n), warp tile 32x64.
// K chunks of 32; per-stage buffers 128 rows x 40 bf16 (80B pitch).
// ------------------------------------------------------------------
#define KCH       32
#define NCHUNK    8                     /* 256 / 32 */
#define PITCH     40                    /* bf16 per smem row (32 + 8 pad) */
#define BUF_B     (128 * PITCH * 2)     /* 10240 bytes per buffer */
#define STAGE_B   (4 * BUF_B)           /* 40960 bytes per stage */
#define GSM_TOTAL (2 * STAGE_B)         /* 81920 bytes */

__global__ __launch_bounds__(256) void mma_gemm_kernel(
    const __nv_bfloat16* __restrict__ Ahi, const __nv_bfloat16* __restrict__ Alo,
    const __nv_bfloat16* __restrict__ Bhi, const __nv_bfloat16* __restrict__ Blo,
    float* __restrict__ C, int N) {
    extern __shared__ char smem[];
    uint32_t sbase = smem_u32(smem);
    int tid  = threadIdx.x;
    int lane = tid & 31;
    int wid  = tid >> 5;
    int wm   = wid >> 1;        // 0..3
    int wn   = wid & 1;         // 0..1
    int m0   = blockIdx.y * 128;
    int n0   = blockIdx.x * 128;

    float acc[2][8][4];
#pragma unroll
    for (int mt = 0; mt < 2; mt++)
#pragma unroll
        for (int nt = 0; nt < 8; nt++)
#pragma unroll
            for (int j = 0; j < 4; j++) acc[mt][nt][j] = 0.f;

    const uint4* gsrc[4] = {
        (const uint4*)(Ahi + (size_t)m0 * MODEL_DIM),
        (const uint4*)(Alo + (size_t)m0 * MODEL_DIM),
        (const uint4*)(Bhi + (size_t)n0 * MODEL_DIM),
        (const uint4*)(Blo + (size_t)n0 * MODEL_DIM)};

    // loader: chunk ch -> stage st. 2048 x 16B, 8 per thread.
    // idx: b = idx>>9 (buffer), r = (idx>>2)&127 (row), c = idx&3 (16B col)
#define LOAD_CHUNK(ch, st)                                                        \
    do {                                                                          \
        uint32_t stb = sbase + (st) * STAGE_B;                                    \
        _Pragma("unroll")                                                         \
        for (int it = 0; it < 8; it++) {                                          \
            int idx = it * 256 + tid;                                             \
            int b = idx >> 9, r = (idx >> 2) & 127, c = idx & 3;                  \
            CP_ASYNC16(stb + b * BUF_B + r * (PITCH * 2) + c * 16,                \
                       (const void*)(gsrc[b] + (ch) * 4 + (size_t)r * 32 + c));   \
        }                                                                         \
        CP_COMMIT();                                                              \
    } while (0)

    // ldmatrix lane-invariant address pieces
    int a_row_l = lane & 15;                           // + mt*16 + wm*32
    int a_col_l = (lane >> 4) << 3;                    // 0 or 8, + k
    int b_row_l = (lane & 7) + ((lane >> 4) & 1) * 8;  // + p*16 + wn*64
    int b_col_l = ((lane >> 3) & 1) << 3;              // + k

    LOAD_CHUNK(0, 0);

    for (int ch = 0; ch < NCHUNK; ch++) {
        int st = ch & 1;
        if (ch + 1 < NCHUNK) {
            LOAD_CHUNK(ch + 1, st ^ 1);
            CP_WAIT(1);
        } else {
            CP_WAIT(0);
        }
        __syncthreads();

        uint32_t sA_hi = sbase + st * STAGE_B;
        uint32_t sA_lo = sA_hi + BUF_B;
        uint32_t sB_hi = sA_hi + 2 * BUF_B;
        uint32_t sB_lo = sA_hi + 3 * BUF_B;

#pragma unroll
        for (int ks = 0; ks < 2; ks++) {
            int k = ks * 16;
            uint32_t ahi[2][4], alo[2][4], bhi[8][2], blo[8][2];
#pragma unroll
            for (int mt = 0; mt < 2; mt++) {
                uint32_t off = (uint32_t)((wm * 32 + mt * 16 + a_row_l) * (PITCH * 2) +
                                          (k + a_col_l) * 2);
                LDMATRIX_X4(ahi[mt][0], ahi[mt][1], ahi[mt][2], ahi[mt][3], sA_hi + off);
                LDMATRIX_X4(alo[mt][0], alo[mt][1], alo[mt][2], alo[mt][3], sA_lo + off);
            }
#pragma unroll
            for (int p = 0; p < 4; p++) {
                uint32_t off = (uint32_t)((wn * 64 + p * 16 + b_row_l) * (PITCH * 2) +
                                          (k + b_col_l) * 2);
                LDMATRIX_X4(bhi[2 * p][0], bhi[2 * p][1], bhi[2 * p + 1][0], bhi[2 * p + 1][1],
                            sB_hi + off);
                LDMATRIX_X4(blo[2 * p][0], blo[2 * p][1], blo[2 * p + 1][0], blo[2 * p + 1][1],
                            sB_lo + off);
            }
#pragma unroll
            for (int mt = 0; mt < 2; mt++)
#pragma unroll
                for (int nt = 0; nt < 8; nt++) {
                    MMA_BF16(acc[mt][nt], ahi[mt], bhi[nt]);
                    MMA_BF16(acc[mt][nt], ahi[mt], blo[nt]);
                    MMA_BF16(acc[mt][nt], alo[mt], bhi[nt]);
                }
        }
        __syncthreads();
    }
#undef LOAD_CHUNK

    // -- epilogue --
    int gid  = lane >> 2;
    int tq   = lane & 3;
#pragma unroll
    for (int mt = 0; mt < 2; mt++) {
        int row = m0 + wm * 32 + mt * 16 + gid;
#pragma unroll
        for (int nt = 0; nt < 8; nt++) {
            int col = n0 + wn * 64 + nt * 8 + tq * 2;
            *(float2*)(C + (size_t)row * N + col)       = make_float2(acc[mt][nt][0], acc[mt][nt][1]);
            *(float2*)(C + (size_t)(row + 8) * N + col) = make_float2(acc[mt][nt][2], acc[mt][nt][3]);
        }
    }
}

// ------------------------------------------------------------------
// K3: rotary on q[...,0:32] and k channels [256,288) of g_qkv
// ------------------------------------------------------------------
__global__ __launch_bounds__(256) void rotary_kernel() {
    int row = blockIdx.x * 8 + threadIdx.y;
    int d   = threadIdx.x;
    int y   = row & 127;
    int x   = (row >> 7) & 127;
    int j   = (d & 15) >> 1;
    int pos = (d < 16) ? x : y;
    float invf = exp2f(-(float)j * 1.6609640474436813f);
    float t    = (float)pos * (2.0f / 127.0f) - 1.0f;
    float f    = t * invf;
    float c = cosf(f), s = sinf(f);

    float* qp = g_qkv + (size_t)row * QKV_DIM;
    float qv = qp[d];
    float kv = qp[256 + d];
    float qpart = __shfl_xor_sync(0xffffffffu, qv, 1);
    float kpart = __shfl_xor_sync(0xffffffffu, kv, 1);
    float qrot = (d & 1) ? qpart : -qpart;
    float krot = (d & 1) ? kpart : -kpart;
    qp[d]       = qv * c + qrot * s;
    qp[256 + d] = kv * c + krot * s;
}

// ------------------------------------------------------------------
// K4: attention per (b,x,h). 128 threads = one per query row.
// ------------------------------------------------------------------
__global__ __launch_bounds__(128) void attn_kernel(const void* __restrict__ mask_raw) {
    extern __shared__ float sm[];
    float* Ks = sm;
    float* Vs = Ks + 128 * 32;
    float* Ss = Vs + 128 * 32;
    float* Mb = Ss + 128 * 129;

    int h   = blockIdx.x & 7;
    int bx  = blockIdx.x >> 3;
    int tid = threadIdx.x;
    size_t base = (size_t)bx * 128;
    int off = h * HEAD_DIM;

    for (int i = tid; i < 128 * 8; i += 128) {
        int r  = i >> 3;
        int f4 = (i & 7) * 4;
        const float* src = g_qkv + (base + r) * QKV_DIM;
        *(float4*)(Ks + r * 32 + f4) = *(const float4*)(src + 256 + off + f4);
        *(float4*)(Vs + r * 32 + f4) = *(const float4*)(src + 512 + off + f4);
    }
    {
        size_t mi = (size_t)bx * 128 + tid;
        unsigned mv = g_mask_is_u8 ? (unsigned)((const unsigned char*)mask_raw)[mi]
                                   : ((const unsigned int*)mask_raw)[mi];
        Mb[tid] = (mv != 0u) ? 1.0f : 0.0f;
    }

    float q[32];
    const float* qsrc = g_qkv + (base + tid) * QKV_DIM + off;
#pragma unroll
    for (int i = 0; i < 8; i++) *(float4*)(q + i * 4) = *(const float4*)(qsrc + i * 4);
    __syncthreads();

    float* srow = Ss + tid * 129;
    float m = -3.0e38f;
    for (int k = 0; k < 128; k++) {
        float dot = 0.f;
#pragma unroll
        for (int d = 0; d < 32; d += 4) {
            float4 kv = *(const float4*)(Ks + k * 32 + d);
            dot += q[d] * kv.x + q[d + 1] * kv.y + q[d + 2] * kv.z + q[d + 3] * kv.w;
        }
        float sc = (Mb[k] != 0.f) ? MASK_BIAS : dot * SCALE;
        srow[k] = sc;
        m = fmaxf(m, sc);
    }
    float sum = 0.f;
    for (int k = 0; k < 128; k++) {
        float p = __expf(srow[k] - m);
        srow[k] = p;
        sum += p;
    }
    float inv = 1.0f / sum;

    float acc[32];
#pragma unroll
    for (int d = 0; d < 32; d++) acc[d] = 0.f;
    for (int k = 0; k < 128; k++) {
        float p = srow[k];
#pragma unroll
        for (int d = 0; d < 32; d += 4) {
            float4 v = *(const float4*)(Vs + k * 32 + d);
            acc[d]     += p * v.x;
            acc[d + 1] += p * v.y;
            acc[d + 2] += p * v.z;
            acc[d + 3] += p * v.w;
        }
    }
    float* dst = g_attno + (base + tid) * MODEL_DIM + off;
#pragma unroll
    for (int i = 0; i < 8; i++) {
        float4 v = make_float4(acc[i * 4] * inv, acc[i * 4 + 1] * inv,
                               acc[i * 4 + 2] * inv, acc[i * 4 + 3] * inv);
        *(float4*)(dst + i * 4) = v;
    }
}

// ------------------------------------------------------------------
extern "C" void kernel_launch(void* const* d_in, const int* in_sizes, int n_in,
                              void* d_out, int out_size) {
    const float* pair_act  = (const float*)d_in[0];
    const void*  pair_mask = (const void*)d_in[1];
    const float* ln_gamma  = (const float*)d_in[2];
    const float* ln_beta   = (const float*)d_in[3];
    const float* Wqkv      = (const float*)d_in[4];
    const float* Wout      = (const float*)d_in[5];
    float*       out       = (float*)d_out;

    (void)in_sizes; (void)n_in; (void)out_size;

    cudaFuncSetAttribute(attn_kernel, cudaFuncAttributeMaxDynamicSharedMemorySize, 99328);
    cudaFuncSetAttribute(mma_gemm_kernel, cudaFuncAttributeMaxDynamicSharedMemorySize, GSM_TOTAL);

    __nv_bfloat16 *xhi, *xlo, *ohi, *olo, *whi, *wlo, *wohi, *wolo;
    float *qkv, *attno;
    cudaGetSymbolAddress((void**)&xhi, g_xhi);
    cudaGetSymbolAddress((void**)&xlo, g_xlo);
    cudaGetSymbolAddress((void**)&ohi, g_ohi);
    cudaGetSymbolAddress((void**)&olo, g_olo);
    cudaGetSymbolAddress((void**)&whi, g_whi);
    cudaGetSymbolAddress((void**)&wlo, g_wlo);
    cudaGetSymbolAddress((void**)&wohi, g_wohi);
    cudaGetSymbolAddress((void**)&wolo, g_wolo);
    cudaGetSymbolAddress((void**)&qkv, g_qkv);
    cudaGetSymbolAddress((void**)&attno, g_attno);

    mask_detect_kernel<<<1, 256>>>((const unsigned char*)pair_mask);
    ln_conv_kernel<<<ROWS / 8, dim3(32, 8)>>>(pair_act, ln_gamma, ln_beta);
    conv_kernel<<<(QKV_DIM * MODEL_DIM / 4 + 255) / 256, 256>>>(Wqkv, whi, wlo, QKV_DIM * MODEL_DIM / 4);
    conv_kernel<<<(MODEL_DIM * MODEL_DIM / 4 + 255) / 256, 256>>>(Wout, wohi, wolo, MODEL_DIM * MODEL_DIM / 4);

    mma_gemm_kernel<<<dim3(QKV_DIM / 128, ROWS / 128), 256, GSM_TOTAL>>>(
        xhi, xlo, whi, wlo, qkv, QKV_DIM);

    rotary_kernel<<<ROWS / 8, dim3(32, 8)>>>();
    attn_kernel<<<BATCH * SEQ * NUM_HEAD, 128, 99328>>>(pair_mask);

    conv_kernel<<<((int)((size_t)ROWS * MODEL_DIM / 4) + 255) / 256, 256>>>(
        attno, ohi, olo, (int)((size_t)ROWS * MODEL_DIM / 4));
    mma_gemm_kernel<<<dim3(MODEL_DIM / 128, ROWS / 128), 256, GSM_TOTAL>>>(
        ohi, olo, wohi, wolo, out, MODEL_DIM);
}

// round 10
// speedup vs baseline: 2.5152x; 1.4766x over previous
#include <cuda_runtime.h>
#include <cuda_bf16.h>
#include <math.h>
#include <stdint.h>

#define MODEL_DIM 256
#define NUM_HEAD  8
#define HEAD_DIM  32
#define SEQ       128
#define BATCH     2
#define ROWS      (BATCH * SEQ * SEQ)   /* 32768 */
#define QKV_DIM   768
#define SCALE     0.17677669529663687f  /* 32^-0.5 */
#define LN_EPS    1e-5f
#define MASK_BIAS -1000000000.0f
#define MASK_N    (BATCH * SEQ * SEQ)

// -------- scratch (static device globals; no runtime allocation) --------
__device__ float g_qkv[(size_t)ROWS * QKV_DIM];            // 96 MB
__device__ __nv_bfloat16 g_xhi[(size_t)ROWS * MODEL_DIM];
__device__ __nv_bfloat16 g_xlo[(size_t)ROWS * MODEL_DIM];
__device__ __nv_bfloat16 g_ohi[(size_t)ROWS * MODEL_DIM];
__device__ __nv_bfloat16 g_olo[(size_t)ROWS * MODEL_DIM];
__device__ __nv_bfloat16 g_whi[QKV_DIM * MODEL_DIM];
__device__ __nv_bfloat16 g_wlo[QKV_DIM * MODEL_DIM];
__device__ __nv_bfloat16 g_wohi[MODEL_DIM * MODEL_DIM];
__device__ __nv_bfloat16 g_wolo[MODEL_DIM * MODEL_DIM];
__device__ unsigned g_mask_is_u8;

__device__ __forceinline__ uint32_t smem_u32(const void* p) {
    uint32_t a;
    asm("{ .reg .u64 t; cvta.to.shared.u64 t, %1; cvt.u32.u64 %0, t; }" : "=r"(a) : "l"(p));
    return a;
}

#define CP_ASYNC16(saddr, gptr) \
    asm volatile("cp.async.cg.shared.global [%0], [%1], 16;" :: "r"(saddr), "l"(gptr))
#define CP_COMMIT() asm volatile("cp.async.commit_group;" ::: "memory")
#define CP_WAIT(n)  asm volatile("cp.async.wait_group %0;" :: "n"(n) : "memory")

#define LDMATRIX_X4(r0, r1, r2, r3, addr) \
    asm volatile("ldmatrix.sync.aligned.m8n8.x4.shared.b16 {%0,%1,%2,%3}, [%4];" \
                 : "=r"(r0), "=r"(r1), "=r"(r2), "=r"(r3) : "r"(addr))

#define LDMATRIX_X4_T(r0, r1, r2, r3, addr) \
    asm volatile("ldmatrix.sync.aligned.m8n8.x4.trans.shared.b16 {%0,%1,%2,%3}, [%4];" \
                 : "=r"(r0), "=r"(r1), "=r"(r2), "=r"(r3) : "r"(addr))

#define MMA_BF16(d, a, b) \
    asm volatile("mma.sync.aligned.m16n8k16.row.col.f32.bf16.bf16.f32 " \
                 "{%0,%1,%2,%3}, {%4,%5,%6,%7}, {%8,%9}, {%0,%1,%2,%3};" \
                 : "+f"((d)[0]), "+f"((d)[1]), "+f"((d)[2]), "+f"((d)[3]) \
                 : "r"((a)[0]), "r"((a)[1]), "r"((a)[2]), "r"((a)[3]), \
                   "r"((b)[0]), "r"((b)[1]))

__device__ __forceinline__ uint32_t pack_bf16x2(float a, float b) {
    __nv_bfloat162 p(__float2bfloat16(a), __float2bfloat16(b));
    return *(uint32_t*)&p;
}

// ------------------------------------------------------------------
// K0: detect mask element width (word widenings of 0/1 have byte i%4==1 zero)
// ------------------------------------------------------------------
__global__ void mask_detect_kernel(const unsigned char* __restrict__ m) {
    __shared__ int any;
    if (threadIdx.x == 0) any = 0;
    __syncthreads();
    int found = 0;
    for (int i = threadIdx.x; i < MASK_N / 4; i += blockDim.x)
        if (m[i * 4 + 1]) found = 1;
    if (found) atomicOr(&any, 1);
    __syncthreads();
    if (threadIdx.x == 0) g_mask_is_u8 = (unsigned)any;
}

// ------------------------------------------------------------------
// K1: fused LayerNorm + split-bf16 conversion. One warp per row of 256.
// ------------------------------------------------------------------
__global__ __launch_bounds__(256) void ln_conv_kernel(const float* __restrict__ x,
                                                      const float* __restrict__ gamma,
                                                      const float* __restrict__ beta) {
    int row  = blockIdx.x * 8 + threadIdx.y;
    int lane = threadIdx.x;
    const float* xr = x + (size_t)row * MODEL_DIM;
    float4 v[2];
    float s = 0.f, s2 = 0.f;
#pragma unroll
    for (int i = 0; i < 2; i++) {
        v[i] = reinterpret_cast<const float4*>(xr)[lane + i * 32];
        s  += v[i].x + v[i].y + v[i].z + v[i].w;
        s2 += v[i].x * v[i].x + v[i].y * v[i].y + v[i].z * v[i].z + v[i].w * v[i].w;
    }
#pragma unroll
    for (int o = 16; o; o >>= 1) {
        s  += __shfl_xor_sync(0xffffffffu, s, o);
        s2 += __shfl_xor_sync(0xffffffffu, s2, o);
    }
    float mu  = s * (1.0f / MODEL_DIM);
    float var = s2 * (1.0f / MODEL_DIM) - mu * mu;
    float rs  = rsqrtf(var + LN_EPS);
#pragma unroll
    for (int i = 0; i < 2; i++) {
        int c0 = (lane + i * 32) * 4;
        float y[4] = {v[i].x, v[i].y, v[i].z, v[i].w};
#pragma unroll
        for (int j = 0; j < 4; j++)
            y[j] = (y[j] - mu) * rs * gamma[c0 + j] + beta[c0 + j];
        __nv_bfloat16 hi[4], lo[4];
#pragma unroll
        for (int j = 0; j < 4; j++) {
            hi[j] = __float2bfloat16(y[j]);
            lo[j] = __float2bfloat16(y[j] - __bfloat162float(hi[j]));
        }
        size_t o0 = (size_t)row * MODEL_DIM + c0;
        *(__nv_bfloat162*)(g_xhi + o0)     = __nv_bfloat162(hi[0], hi[1]);
        *(__nv_bfloat162*)(g_xhi + o0 + 2) = __nv_bfloat162(hi[2], hi[3]);
        *(__nv_bfloat162*)(g_xlo + o0)     = __nv_bfloat162(lo[0], lo[1]);
        *(__nv_bfloat162*)(g_xlo + o0 + 2) = __nv_bfloat162(lo[2], lo[3]);
    }
}

// ------------------------------------------------------------------
// generic fp32 -> split bf16 conversion (weights)
// ------------------------------------------------------------------
__global__ __launch_bounds__(256) void conv_kernel(const float* __restrict__ src,
                                                   __nv_bfloat16* __restrict__ hi,
                                                   __nv_bfloat16* __restrict__ lo, int n4) {
    int i = blockIdx.x * blockDim.x + threadIdx.x;
    if (i >= n4) return;
    float4 v = ((const float4*)src)[i];
    float y[4] = {v.x, v.y, v.z, v.w};
    __nv_bfloat16 h[4], l[4];
#pragma unroll
    for (int j = 0; j < 4; j++) {
        h[j] = __float2bfloat16(y[j]);
        l[j] = __float2bfloat16(y[j] - __bfloat162float(h[j]));
    }
    size_t o0 = (size_t)i * 4;
    *(__nv_bfloat162*)(hi + o0)     = __nv_bfloat162(h[0], h[1]);
    *(__nv_bfloat162*)(hi + o0 + 2) = __nv_bfloat162(h[2], h[3]);
    *(__nv_bfloat162*)(lo + o0)     = __nv_bfloat162(l[0], l[1]);
    *(__nv_bfloat162*)(lo + o0 + 2) = __nv_bfloat162(l[2], l[3]);
}

// ------------------------------------------------------------------
// K2/K5: HMMA split-bf16 GEMM, 2-stage cp.async pipeline (R9, passing).
// ------------------------------------------------------------------
#define KCH       32
#define NCHUNK    8
#define PITCH     40
#define BUF_B     (128 * PITCH * 2)
#define STAGE_B   (4 * BUF_B)
#define GSM_TOTAL (2 * STAGE_B)

__global__ __launch_bounds__(256) void mma_gemm_kernel(
    const __nv_bfloat16* __restrict__ Ahi, const __nv_bfloat16* __restrict__ Alo,
    const __nv_bfloat16* __restrict__ Bhi, const __nv_bfloat16* __restrict__ Blo,
    float* __restrict__ C, int N) {
    extern __shared__ char smem[];
    uint32_t sbase = smem_u32(smem);
    int tid  = threadIdx.x;
    int lane = tid & 31;
    int wid  = tid >> 5;
    int wm   = wid >> 1;
    int wn   = wid & 1;
    int m0   = blockIdx.y * 128;
    int n0   = blockIdx.x * 128;

    float acc[2][8][4];
#pragma unroll
    for (int mt = 0; mt < 2; mt++)
#pragma unroll
        for (int nt = 0; nt < 8; nt++)
#pragma unroll
            for (int j = 0; j < 4; j++) acc[mt][nt][j] = 0.f;

    const uint4* gsrc[4] = {
        (const uint4*)(Ahi + (size_t)m0 * MODEL_DIM),
        (const uint4*)(Alo + (size_t)m0 * MODEL_DIM),
        (const uint4*)(Bhi + (size_t)n0 * MODEL_DIM),
        (const uint4*)(Blo + (size_t)n0 * MODEL_DIM)};

#define LOAD_CHUNK(ch, st)                                                        \
    do {                                                                          \
        uint32_t stb = sbase + (st) * STAGE_B;                                    \
        _Pragma("unroll")                                                         \
        for (int it = 0; it < 8; it++) {                                          \
            int idx = it * 256 + tid;                                             \
            int b = idx >> 9, r = (idx >> 2) & 127, c = idx & 3;                  \
            CP_ASYNC16(stb + b * BUF_B + r * (PITCH * 2) + c * 16,                \
                       (const void*)(gsrc[b] + (ch) * 4 + (size_t)r * 32 + c));   \
        }                                                                         \
        CP_COMMIT();                                                              \
    } while (0)

    int a_row_l = lane & 15;
    int a_col_l = (lane >> 4) << 3;
    int b_row_l = (lane & 7) + ((lane >> 4) & 1) * 8;
    int b_col_l = ((lane >> 3) & 1) << 3;

    LOAD_CHUNK(0, 0);

    for (int ch = 0; ch < NCHUNK; ch++) {
        int st = ch & 1;
        if (ch + 1 < NCHUNK) {
            LOAD_CHUNK(ch + 1, st ^ 1);
            CP_WAIT(1);
        } else {
            CP_WAIT(0);
        }
        __syncthreads();

        uint32_t sA_hi = sbase + st * STAGE_B;
        uint32_t sA_lo = sA_hi + BUF_B;
        uint32_t sB_hi = sA_hi + 2 * BUF_B;
        uint32_t sB_lo = sA_hi + 3 * BUF_B;

#pragma unroll
        for (int ks = 0; ks < 2; ks++) {
            int k = ks * 16;
            uint32_t ahi[2][4], alo[2][4], bhi[8][2], blo[8][2];
#pragma unroll
            for (int mt = 0; mt < 2; mt++) {
                uint32_t off = (uint32_t)((wm * 32 + mt * 16 + a_row_l) * (PITCH * 2) +
                                          (k + a_col_l) * 2);
                LDMATRIX_X4(ahi[mt][0], ahi[mt][1], ahi[mt][2], ahi[mt][3], sA_hi + off);
                LDMATRIX_X4(alo[mt][0], alo[mt][1], alo[mt][2], alo[mt][3], sA_lo + off);
            }
#pragma unroll
            for (int p = 0; p < 4; p++) {
                uint32_t off = (uint32_t)((wn * 64 + p * 16 + b_row_l) * (PITCH * 2) +
                                          (k + b_col_l) * 2);
                LDMATRIX_X4(bhi[2 * p][0], bhi[2 * p][1], bhi[2 * p + 1][0], bhi[2 * p + 1][1],
                            sB_hi + off);
                LDMATRIX_X4(blo[2 * p][0], blo[2 * p][1], blo[2 * p + 1][0], blo[2 * p + 1][1],
                            sB_lo + off);
            }
#pragma unroll
            for (int mt = 0; mt < 2; mt++)
#pragma unroll
                for (int nt = 0; nt < 8; nt++) {
                    MMA_BF16(acc[mt][nt], ahi[mt], bhi[nt]);
                    MMA_BF16(acc[mt][nt], ahi[mt], blo[nt]);
                    MMA_BF16(acc[mt][nt], alo[mt], bhi[nt]);
                }
        }
        __syncthreads();
    }
#undef LOAD_CHUNK

    int gid  = lane >> 2;
    int tq   = lane & 3;
#pragma unroll
    for (int mt = 0; mt < 2; mt++) {
        int row = m0 + wm * 32 + mt * 16 + gid;
#pragma unroll
        for (int nt = 0; nt < 8; nt++) {
            int col = n0 + wn * 64 + nt * 8 + tq * 2;
            *(float2*)(C + (size_t)row * N + col)       = make_float2(acc[mt][nt][0], acc[mt][nt][1]);
            *(float2*)(C + (size_t)(row + 8) * N + col) = make_float2(acc[mt][nt][2], acc[mt][nt][3]);
        }
    }
}

// ------------------------------------------------------------------
// K4: tensorized attention per (b,x,h). 128 threads (4 warps).
// Warp w owns q rows [32w, 32w+32). S = Q K^T via 3-term split HMMA;
// register softmax (m16n8 C layout); P V via 3-term split HMMA with
// C->A fragment reuse and ldmatrix.trans for V. Rotary fused into the
// loader (h==0 only). Emits hi/lo bf16 directly to g_ohi/g_olo.
// ------------------------------------------------------------------
#define APITCH    40                       /* bf16 per smem row */
#define ATILE_B   (128 * APITCH * 2)       /* 10240 bytes */
#define ASM_TOTAL (6 * ATILE_B + 512)      /* + mask floats */

__global__ __launch_bounds__(128) void attn_mma_kernel(const void* __restrict__ mask_raw) {
    extern __shared__ char asmem[];
    uint32_t sb   = smem_u32(asmem);
    uint32_t sQhi = sb;
    uint32_t sQlo = sb + ATILE_B;
    uint32_t sKhi = sb + 2 * ATILE_B;
    uint32_t sKlo = sb + 3 * ATILE_B;
    uint32_t sVhi = sb + 4 * ATILE_B;
    uint32_t sVlo = sb + 5 * ATILE_B;
    float*   Mb   = (float*)(asmem + 6 * ATILE_B);

    int h    = blockIdx.x & 7;
    int bx   = blockIdx.x >> 3;
    int tid  = threadIdx.x;
    int lane = tid & 31;
    int w    = tid >> 5;
    size_t base = (size_t)bx * 128;
    int xpos = bx & 127;

    // ---------------- load + rotary + split-convert ----------------
    {
        int r = tid;  // row (y index)
        const float* src = g_qkv + (base + r) * QKV_DIM + h * HEAD_DIM;
        float qv[32], kv[32], vv[32];
#pragma unroll
        for (int i = 0; i < 8; i++) {
            *(float4*)(qv + i * 4) = *(const float4*)(src + i * 4);
            *(float4*)(kv + i * 4) = *(const float4*)(src + 256 + i * 4);
            *(float4*)(vv + i * 4) = *(const float4*)(src + 512 + i * 4);
        }
        if (h == 0) {
#pragma unroll
            for (int pi = 0; pi < 16; pi++) {
                int j   = pi & 7;
                int pos = (pi < 8) ? xpos : r;
                float invf = exp2f(-(float)j * 1.6609640474436813f);
                float t    = (float)pos * (2.0f / 127.0f) - 1.0f;
                float f    = t * invf;
                float c = cosf(f), s = sinf(f);
                float q0 = qv[2 * pi], q1 = qv[2 * pi + 1];
                qv[2 * pi]     = q0 * c - q1 * s;
                qv[2 * pi + 1] = q1 * c + q0 * s;
                float k0 = kv[2 * pi], k1 = kv[2 * pi + 1];
                kv[2 * pi]     = k0 * c - k1 * s;
                kv[2 * pi + 1] = k1 * c + k0 * s;
            }
        }
        char* rowp = asmem + (size_t)r * (APITCH * 2);
#pragma unroll
        for (int i = 0; i < 16; i++) {
            float a, b; __nv_bfloat16 ha, hb;
            a = qv[2 * i]; b = qv[2 * i + 1];
            ha = __float2bfloat16(a); hb = __float2bfloat16(b);
            *(__nv_bfloat162*)(rowp + 0 * ATILE_B + i * 4) = __nv_bfloat162(ha, hb);
            *(__nv_bfloat162*)(rowp + 1 * ATILE_B + i * 4) =
                __nv_bfloat162(__float2bfloat16(a - __bfloat162float(ha)),
                               __float2bfloat16(b - __bfloat162float(hb)));
            a = kv[2 * i]; b = kv[2 * i + 1];
            ha = __float2bfloat16(a); hb = __float2bfloat16(b);
            *(__nv_bfloat162*)(rowp + 2 * ATILE_B + i * 4) = __nv_bfloat162(ha, hb);
            *(__nv_bfloat162*)(rowp + 3 * ATILE_B + i * 4) =
                __nv_bfloat162(__float2bfloat16(a - __bfloat162float(ha)),
                               __float2bfloat16(b - __bfloat162float(hb)));
            a = vv[2 * i]; b = vv[2 * i + 1];
            ha = __float2bfloat16(a); hb = __float2bfloat16(b);
            *(__nv_bfloat162*)(rowp + 4 * ATILE_B + i * 4) = __nv_bfloat162(ha, hb);
            *(__nv_bfloat162*)(rowp + 5 * ATILE_B + i * 4) =
                __nv_bfloat162(__float2bfloat16(a - __bfloat162float(ha)),
                               __float2bfloat16(b - __bfloat162float(hb)));
        }
        size_t mi = base + r;
        unsigned mv = g_mask_is_u8 ? (unsigned)((const unsigned char*)mask_raw)[mi]
                                   : ((const unsigned int*)mask_raw)[mi];
        Mb[r] = (mv != 0u) ? 1.0f : 0.0f;
    }
    __syncthreads();

    // ---------------- S = Q K^T (3-term split) ----------------
    uint32_t aQhi[2][2][4], aQlo[2][2][4];  // [mt][ks][4]
#pragma unroll
    for (int mt = 0; mt < 2; mt++)
#pragma unroll
        for (int ks = 0; ks < 2; ks++) {
            uint32_t off = (uint32_t)((w * 32 + mt * 16 + (lane & 15)) * (APITCH * 2) +
                                      (ks * 16 + ((lane >> 4) << 3)) * 2);
            LDMATRIX_X4(aQhi[mt][ks][0], aQhi[mt][ks][1], aQhi[mt][ks][2], aQhi[mt][ks][3],
                        sQhi + off);
            LDMATRIX_X4(aQlo[mt][ks][0], aQlo[mt][ks][1], aQlo[mt][ks][2], aQlo[mt][ks][3],
                        sQlo + off);
        }

    float c[2][16][4];
#pragma unroll
    for (int mt = 0; mt < 2; mt++)
#pragma unroll
        for (int nt = 0; nt < 16; nt++)
#pragma unroll
            for (int j = 0; j < 4; j++) c[mt][nt][j] = 0.f;

    int kb_row = (lane & 7) + ((lane >> 4) & 1) * 8;
    int kb_col = ((lane >> 3) & 1) << 3;
#pragma unroll
    for (int t = 0; t < 3; t++) {
        uint32_t sK = (t == 1) ? sKlo : sKhi;
#pragma unroll
        for (int ks = 0; ks < 2; ks++) {
            uint32_t bK[16][2];
#pragma unroll
            for (int p = 0; p < 8; p++) {
                uint32_t off = (uint32_t)((p * 16 + kb_row) * (APITCH * 2) +
                                          (ks * 16 + kb_col) * 2);
                LDMATRIX_X4(bK[2 * p][0], bK[2 * p][1], bK[2 * p + 1][0], bK[2 * p + 1][1],
                            sK + off);
            }
#pragma unroll
            for (int mt = 0; mt < 2; mt++) {
                const uint32_t* A = (t == 2) ? aQlo[mt][ks] : aQhi[mt][ks];
#pragma unroll
                for (int nt = 0; nt < 16; nt++) MMA_BF16(c[mt][nt], A, bK[nt]);
            }
        }
    }

    // ---------------- mask + softmax (rows gid, gid+8 per mt) ----------------
#pragma unroll
    for (int mt = 0; mt < 2; mt++) {
        float m0 = -3.0e38f, m1 = -3.0e38f;
#pragma unroll
        for (int nt = 0; nt < 16; nt++) {
#pragma unroll
            for (int jc = 0; jc < 2; jc++) {
                int col = nt * 8 + (lane & 3) * 2 + jc;
                bool mk = (Mb[col] != 0.f);
                float v0 = mk ? MASK_BIAS : c[mt][nt][jc] * SCALE;
                float v1 = mk ? MASK_BIAS : c[mt][nt][jc + 2] * SCALE;
                c[mt][nt][jc]     = v0;
                c[mt][nt][jc + 2] = v1;
                m0 = fmaxf(m0, v0);
                m1 = fmaxf(m1, v1);
            }
        }
        m0 = fmaxf(m0, __shfl_xor_sync(0xffffffffu, m0, 1));
        m0 = fmaxf(m0, __shfl_xor_sync(0xffffffffu, m0, 2));
        m1 = fmaxf(m1, __shfl_xor_sync(0xffffffffu, m1, 1));
        m1 = fmaxf(m1, __shfl_xor_sync(0xffffffffu, m1, 2));
        float s0 = 0.f, s1 = 0.f;
#pragma unroll
        for (int nt = 0; nt < 16; nt++) {
#pragma unroll
            for (int jc = 0; jc < 2; jc++) {
                float p0 = __expf(c[mt][nt][jc] - m0);
                float p1 = __expf(c[mt][nt][jc + 2] - m1);
                c[mt][nt][jc]     = p0;
                c[mt][nt][jc + 2] = p1;
                s0 += p0;
                s1 += p1;
            }
        }
        s0 += __shfl_xor_sync(0xffffffffu, s0, 1);
        s0 += __shfl_xor_sync(0xffffffffu, s0, 2);
        s1 += __shfl_xor_sync(0xffffffffu, s1, 1);
        s1 += __shfl_xor_sync(0xffffffffu, s1, 2);
        float i0 = 1.0f / s0, i1 = 1.0f / s1;
#pragma unroll
        for (int nt = 0; nt < 16; nt++) {
            c[mt][nt][0] *= i0;
            c[mt][nt][1] *= i0;
            c[mt][nt][2] *= i1;
            c[mt][nt][3] *= i1;
        }
    }

    // ---------------- O = P V (3-term split) ----------------
    float o[2][4][4];
#pragma unroll
    for (int mt = 0; mt < 2; mt++)
#pragma unroll
        for (int nt = 0; nt < 4; nt++)
#pragma unroll
            for (int j = 0; j < 4; j++) o[mt][nt][j] = 0.f;

    int vb_row = (lane & 7) + ((lane >> 3) & 1) * 8;
    int vb_col = (lane >> 4) << 3;
#pragma unroll
    for (int ks = 0; ks < 8; ks++) {
        uint32_t bVhi[4][2], bVlo[4][2];
#pragma unroll
        for (int nb = 0; nb < 2; nb++) {
            uint32_t off = (uint32_t)((ks * 16 + vb_row) * (APITCH * 2) +
                                      (nb * 16 + vb_col) * 2);
            LDMATRIX_X4_T(bVhi[2 * nb][0], bVhi[2 * nb][1], bVhi[2 * nb + 1][0],
                          bVhi[2 * nb + 1][1], sVhi + off);
            LDMATRIX_X4_T(bVlo[2 * nb][0], bVlo[2 * nb][1], bVlo[2 * nb + 1][0],
                          bVlo[2 * nb + 1][1], sVlo + off);
        }
#pragma unroll
        for (int mt = 0; mt < 2; mt++) {
            uint32_t phi[4], plo[4];
#pragma unroll
            for (int half = 0; half < 2; half++) {
                const float* cc = c[mt][2 * ks + half];
#pragma unroll
                for (int pr = 0; pr < 2; pr++) {
                    float p0 = cc[pr * 2], p1 = cc[pr * 2 + 1];
                    __nv_bfloat16 h0 = __float2bfloat16(p0), h1 = __float2bfloat16(p1);
                    __nv_bfloat162 hp(h0, h1);
                    phi[half * 2 + pr] = *(uint32_t*)&hp;
                    __nv_bfloat162 lp(__float2bfloat16(p0 - __bfloat162float(h0)),
                                      __float2bfloat16(p1 - __bfloat162float(h1)));
                    plo[half * 2 + pr] = *(uint32_t*)&lp;
                }
            }
#pragma unroll
            for (int nt = 0; nt < 4; nt++) {
                MMA_BF16(o[mt][nt], phi, bVhi[nt]);
                MMA_BF16(o[mt][nt], phi, bVlo[nt]);
                MMA_BF16(o[mt][nt], plo, bVhi[nt]);
            }
        }
    }

    // ---------------- epilogue: split-bf16 store ----------------
    int gid = lane >> 2, tq = lane & 3;
#pragma unroll
    for (int mt = 0; mt < 2; mt++) {
        int row0 = w * 32 + mt * 16 + gid;
#pragma unroll
        for (int nt = 0; nt < 4; nt++) {
            int col = h * 32 + nt * 8 + tq * 2;
            size_t off0 = (base + row0) * MODEL_DIM + col;
            size_t off1 = (base + row0 + 8) * MODEL_DIM + col;
            float v0 = o[mt][nt][0], v1 = o[mt][nt][1];
            float v2 = o[mt][nt][2], v3 = o[mt][nt][3];
            __nv_bfloat16 h0 = __float2bfloat16(v0), h1 = __float2bfloat16(v1);
            __nv_bfloat16 h2 = __float2bfloat16(v2), h3 = __float2bfloat16(v3);
            *(__nv_bfloat162*)(g_ohi + off0) = __nv_bfloat162(h0, h1);
            *(__nv_bfloat162*)(g_ohi + off1) = __nv_bfloat162(h2, h3);
            *(__nv_bfloat162*)(g_olo + off0) =
                __nv_bfloat162(__float2bfloat16(v0 - __bfloat162float(h0)),
                               __float2bfloat16(v1 - __bfloat162float(h1)));
            *(__nv_bfloat162*)(g_olo + off1) =
                __nv_bfloat162(__float2bfloat16(v2 - __bfloat162float(h2)),
                               __float2bfloat16(v3 - __bfloat162float(h3)));
        }
    }
}

// ------------------------------------------------------------------
extern "C" void kernel_launch(void* const* d_in, const int* in_sizes, int n_in,
                              void* d_out, int out_size) {
    const float* pair_act  = (const float*)d_in[0];
    const void*  pair_mask = (const void*)d_in[1];
    const float* ln_gamma  = (const float*)d_in[2];
    const float* ln_beta   = (const float*)d_in[3];
    const float* Wqkv      = (const float*)d_in[4];
    const float* Wout      = (const float*)d_in[5];
    float*       out       = (float*)d_out;

    (void)in_sizes; (void)n_in; (void)out_size;

    cudaFuncSetAttribute(mma_gemm_kernel, cudaFuncAttributeMaxDynamicSharedMemorySize, GSM_TOTAL);
    cudaFuncSetAttribute(attn_mma_kernel, cudaFuncAttributeMaxDynamicSharedMemorySize, ASM_TOTAL);

    __nv_bfloat16 *xhi, *xlo, *ohi, *olo, *whi, *wlo, *wohi, *wolo;
    float *qkv;
    cudaGetSymbolAddress((void**)&xhi, g_xhi);
    cudaGetSymbolAddress((void**)&xlo, g_xlo);
    cudaGetSymbolAddress((void**)&ohi, g_ohi);
    cudaGetSymbolAddress((void**)&olo, g_olo);
    cudaGetSymbolAddress((void**)&whi, g_whi);
    cudaGetSymbolAddress((void**)&wlo, g_wlo);
    cudaGetSymbolAddress((void**)&wohi, g_wohi);
    cudaGetSymbolAddress((void**)&wolo, g_wolo);
    cudaGetSymbolAddress((void**)&qkv, g_qkv);

    mask_detect_kernel<<<1, 256>>>((const unsigned char*)pair_mask);
    ln_conv_kernel<<<ROWS / 8, dim3(32, 8)>>>(pair_act, ln_gamma, ln_beta);
    conv_kernel<<<(QKV_DIM * MODEL_DIM / 4 + 255) / 256, 256>>>(Wqkv, whi, wlo, QKV_DIM * MODEL_DIM / 4);
    conv_kernel<<<(MODEL_DIM * MODEL_DIM / 4 + 255) / 256, 256>>>(Wout, wohi, wolo, MODEL_DIM * MODEL_DIM / 4);

    mma_gemm_kernel<<<dim3(QKV_DIM / 128, ROWS / 128), 256, GSM_TOTAL>>>(
        xhi, xlo, whi, wlo, qkv, QKV_DIM);

    attn_mma_kernel<<<BATCH * SEQ * NUM_HEAD, 128, ASM_TOTAL>>>(pair_mask);

    mma_gemm_kernel<<<dim3(MODEL_DIM / 128, ROWS / 128), 256, GSM_TOTAL>>>(
        ohi, olo, wohi, wolo, out, MODEL_DIM);
}